// round 2
// baseline (speedup 1.0000x reference)
#include <cuda_runtime.h>
#include <math.h>

#define Bb 2
#define Nn 5
#define Kk 5
#define Qq 75
#define Tt 196
#define Cc 384
#define Ssz (Kk*Tt)   /* 980 */
#define TEMPF 10.0f

typedef unsigned long long u64;

// Scratch for normalized features (device globals: allocation-guard safe).
__device__ __align__(16) float g_Qn[Bb*Qq*Tt*Cc];   // [b][q][t][c]
__device__ __align__(16) float g_Sn[Bb*Nn*Ssz*Cc];  // [b][n][s][c]

__device__ __forceinline__ u64 ffma2(u64 a, u64 b, u64 c) {
    u64 d;
    asm("fma.rn.f32x2 %0, %1, %2, %3;" : "=l"(d) : "l"(a), "l"(b), "l"(c));
    return d;
}

// ---------------- row L2 normalization (one warp per row of 384) -------------
__device__ __forceinline__ void norm_rows_body(const float* __restrict__ in,
                                               float* __restrict__ out,
                                               int rows, float eps) {
    int row = blockIdx.x * 4 + (threadIdx.x >> 5);
    if (row >= rows) return;
    int lane = threadIdx.x & 31;
    const float4* ip = (const float4*)(in + (size_t)row * Cc) + lane;
    float4 v0 = ip[0], v1 = ip[32], v2 = ip[64];
    float ss = v0.x*v0.x + v0.y*v0.y + v0.z*v0.z + v0.w*v0.w
             + v1.x*v1.x + v1.y*v1.y + v1.z*v1.z + v1.w*v1.w
             + v2.x*v2.x + v2.y*v2.y + v2.z*v2.z + v2.w*v2.w;
    #pragma unroll
    for (int o = 16; o; o >>= 1) ss += __shfl_xor_sync(0xffffffffu, ss, o);
    float s = 1.0f / fmaxf(sqrtf(ss), eps);
    float4* op = (float4*)(out + (size_t)row * Cc) + lane;
    v0.x*=s; v0.y*=s; v0.z*=s; v0.w*=s;
    v1.x*=s; v1.y*=s; v1.z*=s; v1.w*=s;
    v2.x*=s; v2.y*=s; v2.z*=s; v2.w*=s;
    op[0] = v0; op[32] = v1; op[64] = v2;
}

__global__ void norm_q_kernel(const float* __restrict__ in) {
    norm_rows_body(in, g_Qn, Bb*Qq*Tt, 1e-8f);
}
__global__ void norm_s_kernel(const float* __restrict__ in) {
    norm_rows_body(in, g_Sn, Bb*Nn*Ssz, 1e-8f);
}

// ---------------- main: sim GEMM + max over s + mean over t ------------------
// One CTA per (b,q,n). 256 threads: tn = tid&7 (s-cols), tm = tid>>3 (t-rows).
// Thread micro-tile: 7 rows (t = tm + 32*i) x 8 cols (s = s0 + tn + 8*j).
#define PCH 16       // float2 pairs per c-chunk (chunk = 32 channels)
#define NTile 64
#define QPAD 225
#define SPAD 65

__global__ __launch_bounds__(256, 1) void sim_kernel(float* __restrict__ out) {
    const int n = blockIdx.x, q = blockIdx.y, b = blockIdx.z;
    const float* Qb = g_Qn + (size_t)(b*Qq + q) * Tt * Cc;
    const float* Sb = g_Sn + (size_t)(b*Nn + n) * Ssz * Cc;

    __shared__ u64 Qs[PCH][QPAD];   // [pair][t]   t in [0,224)
    __shared__ u64 Ssm[PCH][SPAD];  // [pair][sl]  sl in [0,64)
    __shared__ float red[8];

    const int tid = threadIdx.x;
    const int tn = tid & 7, tm = tid >> 3;

    float vmax[7];
    #pragma unroll
    for (int i = 0; i < 7; i++) vmax[i] = -1e30f;

    for (int s0 = 0; s0 < Ssz; s0 += NTile) {
        u64 acc[7][8];
        #pragma unroll
        for (int i = 0; i < 7; i++)
            #pragma unroll
            for (int j = 0; j < 8; j++) acc[i][j] = 0ull;

        for (int c0 = 0; c0 < Cc; c0 += 2*PCH) {
            __syncthreads();
            // stage Q chunk (transposed pairs): Qs[p][t] = {Q[t][c0+2p], Q[t][c0+2p+1]}
            for (int idx = tid; idx < PCH*224; idx += 256) {
                int p = idx & 15, t = idx >> 4;
                u64 v = 0ull;
                if (t < Tt) v = *(const u64*)(Qb + (size_t)t*Cc + c0 + 2*p);
                Qs[p][t] = v;
            }
            // stage S chunk
            for (int idx = tid; idx < PCH*NTile; idx += 256) {
                int p = idx & 15, sl = idx >> 4;
                int s = s0 + sl;
                u64 v = 0ull;
                if (s < Ssz) v = *(const u64*)(Sb + (size_t)s*Cc + c0 + 2*p);
                Ssm[p][sl] = v;
            }
            __syncthreads();

            #pragma unroll
            for (int p = 0; p < PCH; p++) {
                u64 qv[7], sv[8];
                #pragma unroll
                for (int i = 0; i < 7; i++) qv[i] = Qs[p][tm + 32*i];
                #pragma unroll
                for (int j = 0; j < 8; j++) sv[j] = Ssm[p][tn + 8*j];
                #pragma unroll
                for (int i = 0; i < 7; i++)
                    #pragma unroll
                    for (int j = 0; j < 8; j++)
                        acc[i][j] = ffma2(qv[i], sv[j], acc[i][j]);
            }
        }

        // fold this s-tile into running per-row max
        #pragma unroll
        for (int i = 0; i < 7; i++)
            #pragma unroll
            for (int j = 0; j < 8; j++) {
                int s = s0 + tn + 8*j;
                if (s < Ssz) {
                    float lo = __uint_as_float((unsigned)(acc[i][j] & 0xffffffffull));
                    float hi = __uint_as_float((unsigned)(acc[i][j] >> 32));
                    vmax[i] = fmaxf(vmax[i], lo + hi);
                }
            }
    }

    // max across the 8 column-owner lanes (contiguous lanes sharing tm)
    #pragma unroll
    for (int i = 0; i < 7; i++) {
        float v = vmax[i];
        v = fmaxf(v, __shfl_xor_sync(0xffffffffu, v, 1));
        v = fmaxf(v, __shfl_xor_sync(0xffffffffu, v, 2));
        v = fmaxf(v, __shfl_xor_sync(0xffffffffu, v, 4));
        vmax[i] = v;
    }
    // sum of per-row maxes over valid t
    float partial = 0.f;
    if (tn == 0) {
        #pragma unroll
        for (int i = 0; i < 7; i++) {
            int t = tm + 32*i;
            if (t < Tt) partial += vmax[i];
        }
    }
    #pragma unroll
    for (int o = 16; o; o >>= 1) partial += __shfl_xor_sync(0xffffffffu, partial, o);
    if ((tid & 31) == 0) red[tid >> 5] = partial;
    __syncthreads();
    if (tid == 0) {
        float tot = 0.f;
        #pragma unroll
        for (int w = 0; w < 8; w++) tot += red[w];
        out[(size_t)(b*Qq + q)*Nn + n] = tot / (float)Tt;
    }
}

// ---------------- classifier branch (prototype cosine * TEMP) ----------------
__global__ void cls_kernel(const float* __restrict__ xs,   // [b][n][k][c]
                           const float* __restrict__ xq,   // [b][q][c]
                           float* __restrict__ out) {
    int bq = blockIdx.x;
    int b = bq / Qq, q = bq % Qq;
    int tid = threadIdx.x;                 // 128 threads
    int lane = tid & 31, wid = tid >> 5;
    __shared__ float sm[8];
    __shared__ float s_sqq;

    const float* xqr = xq + (size_t)(b*Qq + q) * Cc;
    float qv[3];
    float sqq = 0.f;
    #pragma unroll
    for (int j = 0; j < 3; j++) {
        qv[j] = xqr[tid + 128*j];
        sqq += qv[j]*qv[j];
    }
    float r = sqq;
    #pragma unroll
    for (int o = 16; o; o >>= 1) r += __shfl_xor_sync(0xffffffffu, r, o);
    if (lane == 0) sm[wid] = r;
    __syncthreads();
    if (tid == 0) s_sqq = sm[0] + sm[1] + sm[2] + sm[3];
    __syncthreads();

    for (int n = 0; n < Nn; n++) {
        float spp = 0.f, sqp = 0.f;
        #pragma unroll
        for (int j = 0; j < 3; j++) {
            int c = tid + 128*j;
            const float* xsr = xs + (size_t)(b*Nn + n) * Kk * Cc + c;
            float pv = 0.f;
            #pragma unroll
            for (int k = 0; k < Kk; k++) pv += xsr[(size_t)k*Cc];
            pv *= 0.2f;                     // mean over k shots
            spp += pv*pv;
            sqp += qv[j]*pv;
        }
        float a = spp, d = sqp;
        #pragma unroll
        for (int o = 16; o; o >>= 1) {
            a += __shfl_xor_sync(0xffffffffu, a, o);
            d += __shfl_xor_sync(0xffffffffu, d, o);
        }
        if (lane == 0) { sm[wid] = a; sm[4 + wid] = d; }
        __syncthreads();
        if (tid == 0) {
            float PP = sm[0] + sm[1] + sm[2] + sm[3];
            float QP = sm[4] + sm[5] + sm[6] + sm[7];
            float denom = fmaxf(sqrtf(s_sqq), 1e-12f) * fmaxf(sqrtf(PP), 1e-12f);
            out[(size_t)Bb*Qq*Nn + (size_t)(b*Qq + q)*Nn + n] = TEMPF * QP / denom;
        }
        __syncthreads();
    }
}

// -----------------------------------------------------------------------------
extern "C" void kernel_launch(void* const* d_in, const int* in_sizes, int n_in,
                              void* d_out, int out_size) {
    const float *fs = nullptr, *fq = nullptr, *xs = nullptr, *xq = nullptr;
    for (int i = 0; i < n_in; i++) {
        long long sz = in_sizes[i];
        if      (sz == (long long)Bb*Nn*Kk*Tt*Cc) fs = (const float*)d_in[i];
        else if (sz == (long long)Bb*Qq*Tt*Cc)    fq = (const float*)d_in[i];
        else if (sz == (long long)Bb*Nn*Kk*Cc)    xs = (const float*)d_in[i];
        else if (sz == (long long)Bb*Qq*Cc)       xq = (const float*)d_in[i];
    }
    float* out = (float*)d_out;

    norm_q_kernel<<<(Bb*Qq*Tt + 3) / 4, 128>>>(fq);
    norm_s_kernel<<<(Bb*Nn*Ssz + 3) / 4, 128>>>(fs);
    sim_kernel<<<dim3(Nn, Qq, Bb), 256>>>(out);
    cls_kernel<<<Bb*Qq, 128>>>(xs, xq, out);
}

// round 8
// speedup vs baseline: 6.4134x; 6.4134x over previous
#include <cuda_runtime.h>
#include <math.h>
#include <stdint.h>

#define Bb 2
#define Nn 5
#define Kk 5
#define Qq 75
#define Tt 196
#define Cc 384
#define Ssz (Kk*Tt)        /* 980 */
#define MQ  (Qq*Tt)        /* 14700 rows per batch */
#define MQP 14848          /* padded M per batch (58*256) */
#define SSP 1024           /* padded S per (b,n) */
#define MTILES 58          /* per batch, tile 256 */
#define NTILES 8           /* 1024/128 */
#define KCH 12             /* 384/32 */
#define RMSTRIDE 14720
#define TEMPF 10.0f

// dynamic smem layout (bytes, after 1KB alignment)
#define OFF_A0 0
#define OFF_B0 32768
#define OFF_A1 49152
#define OFF_B1 81920
#define OFF_RED 98304
#define SMEM_BYTES (98304 + 2048 + 1024)

// ---------------- scratch (device globals: allocation-guard safe) ------------
__device__ __align__(16) float g_Qn[Bb*MQP*Cc];       // [b][m(pad)][c] tf32-rounded
__device__ __align__(16) float g_Sn[Bb*Nn*SSP*Cc];    // [bn][s(pad)][c] tf32-rounded
__device__ __align__(16) float g_rowmax[Bb*Nn*RMSTRIDE];

// ---------------- helpers ----------------------------------------------------
__device__ __forceinline__ uint32_t smem_u32(const void* p) {
    uint32_t a;
    asm("{ .reg .u64 t; cvta.to.shared.u64 t, %1; cvt.u32.u64 %0, t; }" : "=r"(a) : "l"(p));
    return a;
}
__device__ __forceinline__ void cp16(uint32_t saddr, const void* g) {
    asm volatile("cp.async.cg.shared.global [%0], [%1], 16;" :: "r"(saddr), "l"(g));
}
__device__ __forceinline__ void cp_commit() {
    asm volatile("cp.async.commit_group;" ::: "memory");
}
__device__ __forceinline__ void cp_wait1() {
    asm volatile("cp.async.wait_group 1;" ::: "memory");
}
__device__ __forceinline__ void cp_wait0() {
    asm volatile("cp.async.wait_group 0;" ::: "memory");
}
__device__ __forceinline__ float ldsf(uint32_t a) {
    float v; asm("ld.shared.f32 %0, [%1];" : "=f"(v) : "r"(a)); return v;
}
__device__ __forceinline__ float tf32r(float x) {
    uint32_t u; asm("cvt.rna.tf32.f32 %0, %1;" : "=r"(u) : "f"(x));
    return __uint_as_float(u);
}
__device__ __forceinline__ void mma8(float* c, const float* a, const float* b) {
    asm("mma.sync.aligned.m16n8k8.row.col.f32.tf32.tf32.f32 "
        "{%0,%1,%2,%3}, {%4,%5,%6,%7}, {%8,%9}, {%0,%1,%2,%3};"
        : "+f"(c[0]), "+f"(c[1]), "+f"(c[2]), "+f"(c[3])
        : "r"(__float_as_uint(a[0])), "r"(__float_as_uint(a[1])),
          "r"(__float_as_uint(a[2])), "r"(__float_as_uint(a[3])),
          "r"(__float_as_uint(b[0])), "r"(__float_as_uint(b[1])));
}

// ---------------- row L2 normalization + tf32 rounding -----------------------
__device__ __forceinline__ void norm_rows_body(const float* __restrict__ in,
                                               float* __restrict__ out,
                                               int rows, int inner, int pad_stride,
                                               float eps) {
    int row = blockIdx.x * 4 + (threadIdx.x >> 5);
    if (row >= rows) return;
    int lane = threadIdx.x & 31;
    int blk = row / inner, r = row - blk * inner;
    const float4* ip = (const float4*)(in + (size_t)row * Cc) + lane;
    float4 v0 = ip[0], v1 = ip[32], v2 = ip[64];
    float ss = v0.x*v0.x + v0.y*v0.y + v0.z*v0.z + v0.w*v0.w
             + v1.x*v1.x + v1.y*v1.y + v1.z*v1.z + v1.w*v1.w
             + v2.x*v2.x + v2.y*v2.y + v2.z*v2.z + v2.w*v2.w;
    #pragma unroll
    for (int o = 16; o; o >>= 1) ss += __shfl_xor_sync(0xffffffffu, ss, o);
    float s = 1.0f / fmaxf(sqrtf(ss), eps);
    float4* op = (float4*)(out + ((size_t)blk * pad_stride + r) * Cc) + lane;
    v0.x=tf32r(v0.x*s); v0.y=tf32r(v0.y*s); v0.z=tf32r(v0.z*s); v0.w=tf32r(v0.w*s);
    v1.x=tf32r(v1.x*s); v1.y=tf32r(v1.y*s); v1.z=tf32r(v1.z*s); v1.w=tf32r(v1.w*s);
    v2.x=tf32r(v2.x*s); v2.y=tf32r(v2.y*s); v2.z=tf32r(v2.z*s); v2.w=tf32r(v2.w*s);
    op[0] = v0; op[32] = v1; op[64] = v2;
}
__global__ void norm_q_kernel(const float* __restrict__ in) {
    norm_rows_body(in, g_Qn, Bb*MQ, MQ, MQP, 1e-8f);
}
__global__ void norm_s_kernel(const float* __restrict__ in) {
    norm_rows_body(in, g_Sn, Bb*Nn*Ssz, Ssz, SSP, 1e-8f);
}

// ---------------- tf32 mma.sync GEMM + fused max-over-s ----------------------
// Grid (58 Mtiles, 10 bn), 256 threads = 8 warps as 4(m)x2(n), warp tile 64x64.
__global__ __launch_bounds__(256, 1) void sim_mma_kernel() {
    extern __shared__ char dsm_raw[];
    const uint32_t base = (smem_u32(dsm_raw) + 1023) & ~1023u;

    const int tid = threadIdx.x;
    const int wid = tid >> 5, lane = tid & 31;
    const int wm = wid >> 1, wn = wid & 1;
    const int gid = lane >> 2, tk = lane & 3;
    const int m0 = blockIdx.x * 256;
    const int bn = blockIdx.y;
    const int b  = bn / Nn;

    const float* Ag = g_Qn + ((size_t)b * MQP + m0) * Cc;
    const float* Sg = g_Sn + (size_t)bn * SSP * Cc;

    const uint32_t abuf[2] = { base + OFF_A0, base + OFF_A1 };
    const uint32_t bbuf[2] = { base + OFF_B0, base + OFF_B1 };
    float* red = (float*)(dsm_raw + (base - smem_u32(dsm_raw)) + OFF_RED);

    float rmax[8];
    #pragma unroll
    for (int i = 0; i < 8; i++) rmax[i] = -1e30f;

    for (int nt = 0; nt < NTILES; nt++) {
        const int s0 = nt * 128;
        float acc[4][8][4];
        #pragma unroll
        for (int fm = 0; fm < 4; fm++)
            #pragma unroll
            for (int fn = 0; fn < 8; fn++)
                #pragma unroll
                for (int j = 0; j < 4; j++) acc[fm][fn][j] = 0.f;

        // ---- stage chunk 0 ----
        {
            const int kc = 0;
            #pragma unroll
            for (int it = 0; it < 8; it++) {           // A: 256 rows x 8 units
                int task = tid + it * 256;
                int row = task >> 3, u = task & 7;
                cp16(abuf[0] + row*128 + ((u*16) ^ ((row & 7) << 4)),
                     Ag + (size_t)row * Cc + kc*32 + u*4);
            }
            #pragma unroll
            for (int it = 0; it < 4; it++) {           // B: 128 rows x 8 units
                int task = tid + it * 256;
                int row = task >> 3, u = task & 7;
                cp16(bbuf[0] + row*128 + ((u*16) ^ ((row & 7) << 4)),
                     Sg + (size_t)(s0 + row) * Cc + kc*32 + u*4);
            }
            cp_commit();
        }

        for (int kc = 0; kc < KCH; kc++) {
            const int cur = kc & 1;
            if (kc + 1 < KCH) {
                const int nxt = cur ^ 1, kc1 = kc + 1;
                #pragma unroll
                for (int it = 0; it < 8; it++) {
                    int task = tid + it * 256;
                    int row = task >> 3, u = task & 7;
                    cp16(abuf[nxt] + row*128 + ((u*16) ^ ((row & 7) << 4)),
                         Ag + (size_t)row * Cc + kc1*32 + u*4);
                }
                #pragma unroll
                for (int it = 0; it < 4; it++) {
                    int task = tid + it * 256;
                    int row = task >> 3, u = task & 7;
                    cp16(bbuf[nxt] + row*128 + ((u*16) ^ ((row & 7) << 4)),
                         Sg + (size_t)(s0 + row) * Cc + kc1*32 + u*4);
                }
                cp_commit();
                cp_wait1();
            } else {
                cp_wait0();
            }
            __syncthreads();

            // ---- compute on buf cur ----
            const uint32_t xo = (uint32_t)gid << 4;
            const uint32_t Ab = abuf[cur] + (uint32_t)(wm*64 + gid) * 128;
            const uint32_t Bbse = bbuf[cur] + (uint32_t)(wn*64 + gid) * 128;
            #pragma unroll
            for (int kk = 0; kk < 4; kk++) {
                const uint32_t o0 = (uint32_t)(kk*32 + tk*4) ^ xo;
                const uint32_t o1 = (uint32_t)(kk*32 + tk*4 + 16) ^ xo;
                float afr[4][4];
                #pragma unroll
                for (int fm = 0; fm < 4; fm++) {
                    uint32_t rb = Ab + fm * (16*128);
                    afr[fm][0] = ldsf(rb + o0);
                    afr[fm][1] = ldsf(rb + 8*128 + o0);
                    afr[fm][2] = ldsf(rb + o1);
                    afr[fm][3] = ldsf(rb + 8*128 + o1);
                }
                float bfr[8][2];
                #pragma unroll
                for (int fn = 0; fn < 8; fn++) {
                    uint32_t rb = Bbse + fn * (8*128);
                    bfr[fn][0] = ldsf(rb + o0);
                    bfr[fn][1] = ldsf(rb + o1);
                }
                #pragma unroll
                for (int fm = 0; fm < 4; fm++)
                    #pragma unroll
                    for (int fn = 0; fn < 8; fn++)
                        mma8(acc[fm][fn], afr[fm], bfr[fn]);
            }
            __syncthreads();
        }

        // ---- fold tile into running row maxes (mask s >= Ssz) ----
        #pragma unroll
        for (int fn = 0; fn < 8; fn++) {
            int sc = s0 + wn*64 + fn*8 + tk*2;
            bool v0 = (sc < Ssz), v1 = (sc + 1 < Ssz);
            #pragma unroll
            for (int fm = 0; fm < 4; fm++) {
                if (v0) {
                    rmax[fm*2+0] = fmaxf(rmax[fm*2+0], acc[fm][fn][0]);
                    rmax[fm*2+1] = fmaxf(rmax[fm*2+1], acc[fm][fn][2]);
                }
                if (v1) {
                    rmax[fm*2+0] = fmaxf(rmax[fm*2+0], acc[fm][fn][1]);
                    rmax[fm*2+1] = fmaxf(rmax[fm*2+1], acc[fm][fn][3]);
                }
            }
        }
    }

    // ---- reduce across tk lanes, then across the 2 n-warps ----
    #pragma unroll
    for (int i = 0; i < 8; i++) {
        float v = rmax[i];
        v = fmaxf(v, __shfl_xor_sync(0xffffffffu, v, 1));
        v = fmaxf(v, __shfl_xor_sync(0xffffffffu, v, 2));
        rmax[i] = v;
    }
    __syncthreads();
    if (tk == 0) {
        #pragma unroll
        for (int fm = 0; fm < 4; fm++) {
            red[wn*256 + wm*64 + fm*16 + gid]     = rmax[fm*2+0];
            red[wn*256 + wm*64 + fm*16 + gid + 8] = rmax[fm*2+1];
        }
    }
    __syncthreads();
    {
        int m = m0 + tid;
        if (m < MQ) {
            float v = fmaxf(red[tid], red[256 + tid]);
            g_rowmax[(size_t)bn * RMSTRIDE + m] = v;
        }
    }
}

// ---------------- mean over t ------------------------------------------------
__global__ void reduce_kernel(float* __restrict__ out) {
    int idx = blockIdx.x;                 // (b*Qq+q)*Nn + n
    int n  = idx % Nn;
    int bq = idx / Nn;
    int b  = bq / Qq, q = bq % Qq;
    const float* rm = g_rowmax + (size_t)(b*Nn + n) * RMSTRIDE + (size_t)q * Tt;
    int tid = threadIdx.x;                // 64 threads
    float s = 0.f;
    for (int t = tid; t < Tt; t += 64) s += rm[t];
    #pragma unroll
    for (int o = 16; o; o >>= 1) s += __shfl_xor_sync(0xffffffffu, s, o);
    __shared__ float sm[2];
    if ((tid & 31) == 0) sm[tid >> 5] = s;
    __syncthreads();
    if (tid == 0) out[idx] = (sm[0] + sm[1]) / (float)Tt;
}

// ---------------- classifier branch ------------------------------------------
__global__ void cls_kernel(const float* __restrict__ xs,
                           const float* __restrict__ xq,
                           float* __restrict__ out) {
    int bq = blockIdx.x;
    int b = bq / Qq, q = bq % Qq;
    int tid = threadIdx.x;                 // 128 threads
    int lane = tid & 31, wid = tid >> 5;
    __shared__ float sm[8];
    __shared__ float s_sqq;

    const float* xqr = xq + (size_t)(b*Qq + q) * Cc;
    float qv[3];
    float sqq = 0.f;
    #pragma unroll
    for (int j = 0; j < 3; j++) { qv[j] = xqr[tid + 128*j]; sqq += qv[j]*qv[j]; }
    float r = sqq;
    #pragma unroll
    for (int o = 16; o; o >>= 1) r += __shfl_xor_sync(0xffffffffu, r, o);
    if (lane == 0) sm[wid] = r;
    __syncthreads();
    if (tid == 0) s_sqq = sm[0] + sm[1] + sm[2] + sm[3];
    __syncthreads();

    for (int n = 0; n < Nn; n++) {
        float spp = 0.f, sqp = 0.f;
        #pragma unroll
        for (int j = 0; j < 3; j++) {
            int c = tid + 128*j;
            const float* xsr = xs + (size_t)(b*Nn + n) * Kk * Cc + c;
            float pv = 0.f;
            #pragma unroll
            for (int k = 0; k < Kk; k++) pv += xsr[(size_t)k*Cc];
            pv *= 0.2f;
            spp += pv*pv;
            sqp += qv[j]*pv;
        }
        float a = spp, d = sqp;
        #pragma unroll
        for (int o = 16; o; o >>= 1) {
            a += __shfl_xor_sync(0xffffffffu, a, o);
            d += __shfl_xor_sync(0xffffffffu, d, o);
        }
        if (lane == 0) { sm[wid] = a; sm[4 + wid] = d; }
        __syncthreads();
        if (tid == 0) {
            float PP = sm[0] + sm[1] + sm[2] + sm[3];
            float QP = sm[4] + sm[5] + sm[6] + sm[7];
            float denom = fmaxf(sqrtf(s_sqq), 1e-12f) * fmaxf(sqrtf(PP), 1e-12f);
            out[(size_t)Bb*Qq*Nn + (size_t)(b*Qq + q)*Nn + n] = TEMPF * QP / denom;
        }
        __syncthreads();
    }
}

// -----------------------------------------------------------------------------
extern "C" void kernel_launch(void* const* d_in, const int* in_sizes, int n_in,
                              void* d_out, int out_size) {
    const float *fs = nullptr, *fq = nullptr, *xs = nullptr, *xq = nullptr;
    for (int i = 0; i < n_in; i++) {
        long long sz = in_sizes[i];
        if      (sz == (long long)Bb*Nn*Kk*Tt*Cc) fs = (const float*)d_in[i];
        else if (sz == (long long)Bb*Qq*Tt*Cc)    fq = (const float*)d_in[i];
        else if (sz == (long long)Bb*Nn*Kk*Cc)    xs = (const float*)d_in[i];
        else if (sz == (long long)Bb*Qq*Cc)       xq = (const float*)d_in[i];
    }
    float* out = (float*)d_out;

    cudaFuncSetAttribute(sim_mma_kernel,
                         cudaFuncAttributeMaxDynamicSharedMemorySize, SMEM_BYTES);

    norm_q_kernel<<<(Bb*MQ + 3) / 4, 128>>>(fq);
    norm_s_kernel<<<(Bb*Nn*Ssz + 3) / 4, 128>>>(fs);
    sim_mma_kernel<<<dim3(MTILES, Bb*Nn), 256, SMEM_BYTES>>>();
    reduce_kernel<<<Bb*Qq*Nn, 64>>>(out);
    cls_kernel<<<Bb*Qq, 128>>>(xs, xq, out);
}

// round 10
// speedup vs baseline: 12.0607x; 1.8806x over previous
#include <cuda_runtime.h>
#include <cuda_fp16.h>
#include <math.h>
#include <stdint.h>

#define Bb 2
#define Nn 5
#define Kk 5
#define Qq 75
#define Tt 196
#define Cc 384
#define Ssz (Kk*Tt)        /* 980 */
#define MQ  (Qq*Tt)        /* 14700 rows per batch */
#define MQP 14848          /* padded M per batch (58*256) */
#define SSP 1024           /* padded S per (b,n) */
#define MTILES 58          /* per batch, tile 256 */
#define NTILES 8           /* 1024/128 */
#define KCH 6              /* 384/64 */
#define RMSTRIDE 14720
#define TEMPF 10.0f

// dynamic smem layout (bytes, after 1KB alignment)
#define OFF_A0 0
#define OFF_A1 32768
#define OFF_B0 65536
#define OFF_B1 81920
#define OFF_RED 98304
#define SMEM_BYTES (98304 + 2048 + 1024)

// ---------------- scratch (device globals: allocation-guard safe) ------------
__device__ __align__(16) __half g_Qh[Bb*MQP*Cc];      // [b][m(pad)][c] fp16 normalized
__device__ __align__(16) __half g_Sh[Bb*Nn*SSP*Cc];   // [bn][s(pad)][c]
__device__ __align__(16) float g_rowmax[Bb*Nn*RMSTRIDE];

// ---------------- helpers ----------------------------------------------------
__device__ __forceinline__ uint32_t smem_u32(const void* p) {
    uint32_t a;
    asm("{ .reg .u64 t; cvta.to.shared.u64 t, %1; cvt.u32.u64 %0, t; }" : "=r"(a) : "l"(p));
    return a;
}
__device__ __forceinline__ void cp16(uint32_t saddr, const void* g) {
    asm volatile("cp.async.cg.shared.global [%0], [%1], 16;" :: "r"(saddr), "l"(g));
}
__device__ __forceinline__ void cp_commit() {
    asm volatile("cp.async.commit_group;" ::: "memory");
}
__device__ __forceinline__ void cp_wait1() {
    asm volatile("cp.async.wait_group 1;" ::: "memory");
}
__device__ __forceinline__ void cp_wait0() {
    asm volatile("cp.async.wait_group 0;" ::: "memory");
}
__device__ __forceinline__ void ldsm4(uint32_t* r, uint32_t addr) {
    asm volatile("ldmatrix.sync.aligned.m8n8.x4.shared.b16 {%0,%1,%2,%3}, [%4];"
        : "=r"(r[0]), "=r"(r[1]), "=r"(r[2]), "=r"(r[3]) : "r"(addr));
}
__device__ __forceinline__ void mma16816(float* c, const uint32_t* a,
                                         uint32_t b0, uint32_t b1) {
    asm("mma.sync.aligned.m16n8k16.row.col.f32.f16.f16.f32 "
        "{%0,%1,%2,%3}, {%4,%5,%6,%7}, {%8,%9}, {%0,%1,%2,%3};"
        : "+f"(c[0]), "+f"(c[1]), "+f"(c[2]), "+f"(c[3])
        : "r"(a[0]), "r"(a[1]), "r"(a[2]), "r"(a[3]), "r"(b0), "r"(b1));
}
__device__ __forceinline__ uint32_t h2bits(float x, float y) {
    __half2 h = __floats2half2_rn(x, y);
    return *(uint32_t*)&h;
}

// ---------------- row L2 normalization -> fp16 -------------------------------
__device__ __forceinline__ void norm_rows_h(const float* __restrict__ in,
                                            __half* __restrict__ out,
                                            int rows, int inner, int pad_stride,
                                            float eps) {
    int row = blockIdx.x * 4 + (threadIdx.x >> 5);
    if (row >= rows) return;
    int lane = threadIdx.x & 31;
    int blk = row / inner, r = row - blk * inner;
    const float4* ip = (const float4*)(in + (size_t)row * Cc) + lane;
    float4 v0 = ip[0], v1 = ip[32], v2 = ip[64];
    float ss = v0.x*v0.x + v0.y*v0.y + v0.z*v0.z + v0.w*v0.w
             + v1.x*v1.x + v1.y*v1.y + v1.z*v1.z + v1.w*v1.w
             + v2.x*v2.x + v2.y*v2.y + v2.z*v2.z + v2.w*v2.w;
    #pragma unroll
    for (int o = 16; o; o >>= 1) ss += __shfl_xor_sync(0xffffffffu, ss, o);
    float s = 1.0f / fmaxf(sqrtf(ss), eps);
    uint2* op = (uint2*)(out + ((size_t)blk * pad_stride + r) * Cc);
    uint2 u0, u1, u2;
    u0.x = h2bits(v0.x*s, v0.y*s); u0.y = h2bits(v0.z*s, v0.w*s);
    u1.x = h2bits(v1.x*s, v1.y*s); u1.y = h2bits(v1.z*s, v1.w*s);
    u2.x = h2bits(v2.x*s, v2.y*s); u2.y = h2bits(v2.z*s, v2.w*s);
    op[lane] = u0; op[lane + 32] = u1; op[lane + 64] = u2;
}
__global__ void norm_q_kernel(const float* __restrict__ in) {
    norm_rows_h(in, g_Qh, Bb*MQ, MQ, MQP, 1e-8f);
}
__global__ void norm_s_kernel(const float* __restrict__ in) {
    norm_rows_h(in, g_Sh, Bb*Nn*Ssz, Ssz, SSP, 1e-8f);
}

// ---------------- fp16 mma.sync GEMM + fused max-over-s ----------------------
// Grid (58 Mtiles, 10 bn), 256 threads = 8 warps as 4(m)x2(n), warp tile 64x64.
// K staged in chunks of 64 halves (128B rows, SW128 swizzle), double-buffered.
__global__ __launch_bounds__(256, 1) void sim_mma_kernel() {
    extern __shared__ char dsm_raw[];
    const uint32_t base = (smem_u32(dsm_raw) + 1023) & ~1023u;

    const int tid = threadIdx.x;
    const int wid = tid >> 5, lane = tid & 31;
    const int wm = wid >> 1, wn = wid & 1;
    const int g = lane >> 2, q = lane & 3;
    const int lr = lane & 15;              // ldmatrix row-in-16
    const int lk = (lane >> 4) * 16;       // ldmatrix k-half byte offset
    const uint32_t sw = ((uint32_t)(lane & 7)) << 4;
    const int m0 = blockIdx.x * 256;
    const int bn = blockIdx.y;
    const int b  = bn / Nn;

    const __half* Ag = g_Qh + ((size_t)b * MQP + m0) * Cc;
    const __half* Sg = g_Sh + (size_t)bn * SSP * Cc;

    const uint32_t abuf[2] = { base + OFF_A0, base + OFF_A1 };
    const uint32_t bbuf[2] = { base + OFF_B0, base + OFF_B1 };
    float* red = (float*)(dsm_raw + (base - smem_u32(dsm_raw)) + OFF_RED);

    float rmax[8];
    #pragma unroll
    for (int i = 0; i < 8; i++) rmax[i] = -1e30f;

    for (int nt = 0; nt < NTILES; nt++) {
        const int s0 = nt * 128;
        float acc[4][8][4];
        #pragma unroll
        for (int fm = 0; fm < 4; fm++)
            #pragma unroll
            for (int fn = 0; fn < 8; fn++)
                #pragma unroll
                for (int j = 0; j < 4; j++) acc[fm][fn][j] = 0.f;

        // ---- stage chunk 0 ----
        {
            #pragma unroll
            for (int it = 0; it < 8; it++) {            // A: 256 rows x 8 x 16B
                int task = tid + it * 256;
                int row = task >> 3, u = task & 7;
                cp16(abuf[0] + row*128 + ((u*16) ^ ((row & 7) << 4)),
                     Ag + (size_t)row * Cc + u*8);
            }
            #pragma unroll
            for (int it = 0; it < 4; it++) {            // B: 128 rows x 8 x 16B
                int task = tid + it * 256;
                int row = task >> 3, u = task & 7;
                cp16(bbuf[0] + row*128 + ((u*16) ^ ((row & 7) << 4)),
                     Sg + (size_t)(s0 + row) * Cc + u*8);
            }
            cp_commit();
        }

        for (int kc = 0; kc < KCH; kc++) {
            const int cur = kc & 1;
            if (kc + 1 < KCH) {
                const int nxt = cur ^ 1;
                const size_t coff = (size_t)(kc + 1) * 64;
                #pragma unroll
                for (int it = 0; it < 8; it++) {
                    int task = tid + it * 256;
                    int row = task >> 3, u = task & 7;
                    cp16(abuf[nxt] + row*128 + ((u*16) ^ ((row & 7) << 4)),
                         Ag + (size_t)row * Cc + coff + u*8);
                }
                #pragma unroll
                for (int it = 0; it < 4; it++) {
                    int task = tid + it * 256;
                    int row = task >> 3, u = task & 7;
                    cp16(bbuf[nxt] + row*128 + ((u*16) ^ ((row & 7) << 4)),
                         Sg + (size_t)(s0 + row) * Cc + coff + u*8);
                }
                cp_commit();
                cp_wait1();
            } else {
                cp_wait0();
            }
            __syncthreads();

            // ---- compute on buf cur: 4 k16 steps ----
            const uint32_t Abase = abuf[cur] + (uint32_t)(wm*64 + lr) * 128;
            const uint32_t Bbase = bbuf[cur] + (uint32_t)(wn*64 + lr) * 128;
            #pragma unroll
            for (int kk = 0; kk < 4; kk++) {
                const uint32_t ko = ((uint32_t)(kk*32 + lk)) ^ sw;
                uint32_t afr[4][4], bfr[4][4];
                #pragma unroll
                for (int fm = 0; fm < 4; fm++)
                    ldsm4(afr[fm], Abase + fm*(16*128) + ko);
                #pragma unroll
                for (int fb = 0; fb < 4; fb++)
                    ldsm4(bfr[fb], Bbase + fb*(16*128) + ko);
                #pragma unroll
                for (int fm = 0; fm < 4; fm++)
                    #pragma unroll
                    for (int fn = 0; fn < 8; fn++)
                        mma16816(acc[fm][fn], afr[fm],
                                 bfr[fn >> 1][fn & 1], bfr[fn >> 1][(fn & 1) + 2]);
            }
            __syncthreads();
        }

        // ---- fold tile into running row maxes (mask s >= Ssz) ----
        #pragma unroll
        for (int fn = 0; fn < 8; fn++) {
            int sc = s0 + wn*64 + fn*8 + q*2;
            bool v0 = (sc < Ssz), v1 = (sc + 1 < Ssz);
            #pragma unroll
            for (int fm = 0; fm < 4; fm++) {
                if (v0) {
                    rmax[fm*2+0] = fmaxf(rmax[fm*2+0], acc[fm][fn][0]);
                    rmax[fm*2+1] = fmaxf(rmax[fm*2+1], acc[fm][fn][2]);
                }
                if (v1) {
                    rmax[fm*2+0] = fmaxf(rmax[fm*2+0], acc[fm][fn][1]);
                    rmax[fm*2+1] = fmaxf(rmax[fm*2+1], acc[fm][fn][3]);
                }
            }
        }
    }

    // ---- reduce across the 4 quad lanes (same row), then across 2 n-warps ----
    #pragma unroll
    for (int i = 0; i < 8; i++) {
        float v = rmax[i];
        v = fmaxf(v, __shfl_xor_sync(0xffffffffu, v, 1));
        v = fmaxf(v, __shfl_xor_sync(0xffffffffu, v, 2));
        rmax[i] = v;
    }
    __syncthreads();
    if (q == 0) {
        #pragma unroll
        for (int fm = 0; fm < 4; fm++) {
            red[wn*256 + wm*64 + fm*16 + g]     = rmax[fm*2+0];
            red[wn*256 + wm*64 + fm*16 + g + 8] = rmax[fm*2+1];
        }
    }
    __syncthreads();
    {
        int m = m0 + tid;
        if (m < MQ) {
            float v = fmaxf(red[tid], red[256 + tid]);
            g_rowmax[(size_t)bn * RMSTRIDE + m] = v;
        }
    }
}

// ---------------- mean over t ------------------------------------------------
__global__ void reduce_kernel(float* __restrict__ out) {
    int idx = blockIdx.x;                 // (b*Qq+q)*Nn + n
    int n  = idx % Nn;
    int bq = idx / Nn;
    int b  = bq / Qq, q = bq % Qq;
    const float* rm = g_rowmax + (size_t)(b*Nn + n) * RMSTRIDE + (size_t)q * Tt;
    int tid = threadIdx.x;                // 64 threads
    float s = 0.f;
    for (int t = tid; t < Tt; t += 64) s += rm[t];
    #pragma unroll
    for (int o = 16; o; o >>= 1) s += __shfl_xor_sync(0xffffffffu, s, o);
    __shared__ float sm[2];
    if ((tid & 31) == 0) sm[tid >> 5] = s;
    __syncthreads();
    if (tid == 0) out[idx] = (sm[0] + sm[1]) / (float)Tt;
}

// ---------------- classifier branch ------------------------------------------
__global__ void cls_kernel(const float* __restrict__ xs,
                           const float* __restrict__ xq,
                           float* __restrict__ out) {
    int bq = blockIdx.x;
    int b = bq / Qq, q = bq % Qq;
    int tid = threadIdx.x;                 // 128 threads
    int lane = tid & 31, wid = tid >> 5;
    __shared__ float sm[8];
    __shared__ float s_sqq;

    const float* xqr = xq + (size_t)(b*Qq + q) * Cc;
    float qv[3];
    float sqq = 0.f;
    #pragma unroll
    for (int j = 0; j < 3; j++) { qv[j] = xqr[tid + 128*j]; sqq += qv[j]*qv[j]; }
    float r = sqq;
    #pragma unroll
    for (int o = 16; o; o >>= 1) r += __shfl_xor_sync(0xffffffffu, r, o);
    if (lane == 0) sm[wid] = r;
    __syncthreads();
    if (tid == 0) s_sqq = sm[0] + sm[1] + sm[2] + sm[3];
    __syncthreads();

    for (int n = 0; n < Nn; n++) {
        float spp = 0.f, sqp = 0.f;
        #pragma unroll
        for (int j = 0; j < 3; j++) {
            int c = tid + 128*j;
            const float* xsr = xs + (size_t)(b*Nn + n) * Kk * Cc + c;
            float pv = 0.f;
            #pragma unroll
            for (int k = 0; k < Kk; k++) pv += xsr[(size_t)k*Cc];
            pv *= 0.2f;
            spp += pv*pv;
            sqp += qv[j]*pv;
        }
        float a = spp, d = sqp;
        #pragma unroll
        for (int o = 16; o; o >>= 1) {
            a += __shfl_xor_sync(0xffffffffu, a, o);
            d += __shfl_xor_sync(0xffffffffu, d, o);
        }
        if (lane == 0) { sm[wid] = a; sm[4 + wid] = d; }
        __syncthreads();
        if (tid == 0) {
            float PP = sm[0] + sm[1] + sm[2] + sm[3];
            float QP = sm[4] + sm[5] + sm[6] + sm[7];
            float denom = fmaxf(sqrtf(s_sqq), 1e-12f) * fmaxf(sqrtf(PP), 1e-12f);
            out[(size_t)Bb*Qq*Nn + (size_t)(b*Qq + q)*Nn + n] = TEMPF * QP / denom;
        }
        __syncthreads();
    }
}

// -----------------------------------------------------------------------------
extern "C" void kernel_launch(void* const* d_in, const int* in_sizes, int n_in,
                              void* d_out, int out_size) {
    const float *fs = nullptr, *fq = nullptr, *xs = nullptr, *xq = nullptr;
    for (int i = 0; i < n_in; i++) {
        long long sz = in_sizes[i];
        if      (sz == (long long)Bb*Nn*Kk*Tt*Cc) fs = (const float*)d_in[i];
        else if (sz == (long long)Bb*Qq*Tt*Cc)    fq = (const float*)d_in[i];
        else if (sz == (long long)Bb*Nn*Kk*Cc)    xs = (const float*)d_in[i];
        else if (sz == (long long)Bb*Qq*Cc)       xq = (const float*)d_in[i];
    }
    float* out = (float*)d_out;

    cudaFuncSetAttribute(sim_mma_kernel,
                         cudaFuncAttributeMaxDynamicSharedMemorySize, SMEM_BYTES);

    norm_q_kernel<<<(Bb*MQ + 3) / 4, 128>>>(fq);
    norm_s_kernel<<<(Bb*Nn*Ssz + 3) / 4, 128>>>(fs);
    sim_mma_kernel<<<dim3(MTILES, Bb*Nn), 256, SMEM_BYTES>>>();
    reduce_kernel<<<Bb*Qq*Nn, 64>>>(out);
    cls_kernel<<<Bb*Qq, 128>>>(xs, xq, out);
}